// round 4
// baseline (speedup 1.0000x reference)
#include <cuda_runtime.h>
#include <cstdint>

#define CCH    33
#define KSZ    2112      // 33*8*8
#define FEAT   107
#define IMG    65536     // 256*256
#define QP     9         // patches per block in kernel A
#define SMEM_A (QP * KSZ * 4)

typedef unsigned long long u64;

// SHIFTS / 255 exactly as the reference table (note duplicated [0,8] at j=6)
__constant__ float c_shift[9][2] = {
  {-8.f/255.f,  0.f/255.f}, {-8.f/255.f,  8.f/255.f}, { 0.f/255.f,  8.f/255.f},
  { 8.f/255.f,  8.f/255.f}, { 8.f/255.f,  0.f/255.f}, { 8.f/255.f, -8.f/255.f},
  { 0.f/255.f,  8.f/255.f}, {-8.f/255.f, -8.f/255.f}, { 0.f/255.f,  0.f/255.f}
};

// scratch: patch_feat [32][36][33]
__device__ float g_patch_feat[32 * 36 * 33];

// ---------------------------------------------------------------------------
// f32x2 packed math (Blackwell FFMA2)
// ---------------------------------------------------------------------------
__device__ __forceinline__ u64 fma2(u64 a, u64 b, u64 c) {
  u64 r;
  asm("fma.rn.f32x2 %0, %1, %2, %3;" : "=l"(r) : "l"(a), "l"(b), "l"(c));
  return r;
}
__device__ __forceinline__ u64 pack2(float lo, float hi) {
  u64 r;
  asm("mov.b64 %0, {%1, %2};" : "=l"(r) : "f"(lo), "f"(hi));
  return r;
}
__device__ __forceinline__ void unpack2(u64 v, float& lo, float& hi) {
  asm("mov.b64 {%0, %1}, %2;" : "=f"(lo), "=f"(hi) : "l"(v));
}

// ---------------------------------------------------------------------------
// threefry2x32 (JAX-compatible, 20 rounds) + partitionable uniform
// ---------------------------------------------------------------------------
__device__ __forceinline__ void threefry2x32(uint32_t k0, uint32_t k1,
                                             uint32_t x0, uint32_t x1,
                                             uint32_t& o0, uint32_t& o1)
{
  uint32_t ks[3] = {k0, k1, k0 ^ k1 ^ 0x1BD11BDAu};
  x0 += ks[0]; x1 += ks[1];
  const int R[2][4] = {{13, 15, 26, 6}, {17, 29, 16, 24}};
#pragma unroll
  for (int i = 0; i < 5; ++i) {
#pragma unroll
    for (int r = 0; r < 4; ++r) {
      x0 += x1;
      int rr = R[i & 1][r];
      x1 = (x1 << rr) | (x1 >> (32 - rr));
      x1 ^= x0;
    }
    x0 += ks[(i + 1) % 3];
    x1 += ks[(i + 2) % 3] + (uint32_t)(i + 1);
  }
  o0 = x0; o1 = x1;
}

__device__ __forceinline__ float tf_uniform(uint32_t k0, uint32_t k1, uint32_t g)
{
  uint32_t y0, y1;
  threefry2x32(k0, k1, 0u, g, y0, y1);
  uint32_t bits = y0 ^ y1;
  return __uint_as_float((bits >> 9) | 0x3f800000u) - 1.0f;
}

// ---------------------------------------------------------------------------
// Kernel A: crops + full-contraction conv. grid (4, 32) — 9 patches / block.
// Crop smem layout: pairs (0,1)(2,3)(4,5)(6,7) interleaved (f32x2-ready),
// patch 8 scalar at offset 8*KSZ.
// ---------------------------------------------------------------------------
__global__ __launch_bounds__(256)
void crop_conv_kernel(const float* __restrict__ d, const float* __restrict__ x,
                      const float* __restrict__ conv_w, const float* __restrict__ conv_b)
{
  extern __shared__ float crop[];   // QP * KSZ floats
  __shared__ int s_ix[QP], s_iy[QP];

  const int pg  = blockIdx.x;   // 0..3, patches pg*9 .. pg*9+8
  const int b   = blockIdx.y;
  const int tid = threadIdx.x;

  // -------- parallel per-slot crop coordinates (exact fp order preserved) ----
  if (tid < 36) {
    const int idx = (tid / 9) * (tid % 9);   // target lh index of slot tid
    float lx = x[b * 8 + (idx / 9) * 2 + 0];
    float ly = x[b * 8 + (idx / 9) * 2 + 1];
#pragma unroll
    for (int st = 0; st < 36; ++st) {
      int i = st / 9, j = st % 9;
      if (st <= tid && i * j == idx) { lx += c_shift[j][0]; ly += c_shift[j][1]; }
    }
    int rel = tid - pg * QP;
    if (rel >= 0 && rel < QP) {
      int ix = (int)rintf(lx * 255.f);
      int iy = (int)rintf((ly + 1.0f) * 255.f);
      s_ix[rel] = min(max(ix, 0), 255);
      s_iy[rel] = min(max(iy, 0), 255);
    }
  }
  __syncthreads();

  // -------- gather 9 crops into smem ----------------------------------------
  const float* db = d + (size_t)b * CCH * IMG;
#pragma unroll
  for (int q = 0; q < QP; ++q) {
    int ix = s_ix[q], iy = s_iy[q];
    for (int k = tid; k < KSZ; k += 256) {
      int c = k >> 6, h = (k >> 3) & 7, w = k & 7;
      int r  = ix - 4 + h;
      int cc = iy - 4 + w;
      float v = 0.f;
      if ((unsigned)r < 256u && (unsigned)cc < 256u)
        v = __ldg(db + c * IMG + r * 256 + cc);
      int addr = (q < 8) ? ((q >> 1) * (2 * KSZ) + 2 * k + (q & 1))
                         : (8 * KSZ + k);
      crop[addr] = v;
    }
  }
  __syncthreads();

  // -------- conv: warp w handles outputs o = w + 8t (t<4), warp0 also o=32 ---
  const int warp = tid >> 5, lane = tid & 31;
  u64   acc2[5][4];
  float acc1[5];
#pragma unroll
  for (int t = 0; t < 5; ++t) {
    acc1[t] = 0.f;
#pragma unroll
    for (int pr = 0; pr < 4; ++pr) acc2[t][pr] = pack2(0.f, 0.f);
  }

  const float* wb = conv_w + warp * KSZ;
  for (int k = lane; k < KSZ; k += 32) {
    u64 cp[4];
#pragma unroll
    for (int pr = 0; pr < 4; ++pr)
      cp[pr] = *reinterpret_cast<const u64*>(crop + pr * (2 * KSZ) + 2 * k);
    float c8 = crop[8 * KSZ + k];
#pragma unroll
    for (int t = 0; t < 4; ++t) {
      float w = wb[t * 8 * KSZ + k];
      u64 ww = pack2(w, w);
#pragma unroll
      for (int pr = 0; pr < 4; ++pr) acc2[t][pr] = fma2(cp[pr], ww, acc2[t][pr]);
      acc1[t] = fmaf(c8, w, acc1[t]);
    }
    if (warp == 0) {
      float w = conv_w[32 * KSZ + k];
      u64 ww = pack2(w, w);
#pragma unroll
      for (int pr = 0; pr < 4; ++pr) acc2[4][pr] = fma2(cp[pr], ww, acc2[4][pr]);
      acc1[4] = fmaf(c8, w, acc1[4]);
    }
  }

  // -------- reductions + write patch_feat ------------------------------------
  float* pfb = g_patch_feat + ((size_t)b * 36 + pg * QP) * 33;
#pragma unroll
  for (int t = 0; t < 5; ++t) {
    if (t == 4 && warp != 0) break;
    int o = (t < 4) ? (warp + t * 8) : 32;
#pragma unroll
    for (int pr = 0; pr < 4; ++pr) {
      float lo, hi;
      unpack2(acc2[t][pr], lo, hi);
#pragma unroll
      for (int s = 16; s; s >>= 1) {
        lo += __shfl_xor_sync(0xffffffffu, lo, s);
        hi += __shfl_xor_sync(0xffffffffu, hi, s);
      }
      if (lane == 0) {
        pfb[(pr * 2 + 0) * 33 + o] = lo + conv_b[o];
        pfb[(pr * 2 + 1) * 33 + o] = hi + conv_b[o];
      }
    }
    float s8 = acc1[t];
#pragma unroll
    for (int s = 16; s; s >>= 1) s8 += __shfl_xor_sync(0xffffffffu, s8, s);
    if (lane == 0) pfb[8 * 33 + o] = s8 + conv_b[o];
  }
}

// ---------------------------------------------------------------------------
// Kernel B: fused gin / MP / dropout / heads. 1 block (128 thr) per batch.
// ---------------------------------------------------------------------------
__global__ __launch_bounds__(128)
void tail_kernel(const float* __restrict__ x,
                 const float* __restrict__ H,  const float* __restrict__ T,
                 const float* __restrict__ W,
                 const float* __restrict__ l1w, const float* __restrict__ l1b,
                 const float* __restrict__ l2w, const float* __restrict__ l2b,
                 float* __restrict__ out)
{
  const int b = blockIdx.x, tid = threadIdx.x;
  const int warp = tid >> 5, lane = tid & 31;

  __shared__ float lh[36][2];
  __shared__ float gin[36 * FEAT];
  __shared__ float A[4][16];
  __shared__ float M1s[4][36];
  __shared__ float wsm[11 * FEAT];   // rows 0,1: lin1_w; rows 2..10: lin2_w

  // ---- phase 0: prefetch + independent compute (no syncs) -------------------
  float pf[10];
#pragma unroll
  for (int r = 0; r < 10; ++r) {
    int e = tid + 128 * r;
    pf[r] = (e < 1188) ? g_patch_feat[b * 1188 + e] : 0.f;
  }
#pragma unroll
  for (int r = 0; r < 10; ++r) {
    int e = tid + 128 * r;
    if (e < 11 * FEAT) wsm[e] = (e < 2 * FEAT) ? l1w[e] : l2w[e - 2 * FEAT];
  }
  // threefry split keys (redundant per-thread, hides under loads)
  uint32_t k10, k11, k20, k21;
  threefry2x32(0u, 42u, 0u, 0u, k10, k11);
  threefry2x32(0u, 42u, 0u, 1u, k20, k21);

  // final lh, parallel per index (exact fp order: adds to one index in st order)
  if (tid < 36) {
    float lx = x[b * 8 + (tid / 9) * 2 + 0];
    float ly = x[b * 8 + (tid / 9) * 2 + 1];
#pragma unroll
    for (int st = 0; st < 36; ++st) {
      int i = st / 9, j = st % 9;
      if (i * j == tid) { lx += c_shift[j][0]; ly += c_shift[j][1]; }
    }
    lh[tid][0] = lx; lh[tid][1] = ly;
    gin[tid * FEAT + 105] = lx;
    gin[tid * FEAT + 106] = ly;
  }
  // A = T @ (H*W)   (threads 64..127)
  if (tid >= 64) {
    int p = (tid - 64) >> 4, h = (tid - 64) & 15;
    float wh = W[h], s = 0.f;
    for (int n = 0; n < 36; ++n) s += T[p * 36 + n] * (H[n * 16 + h] * wh);
    A[p][h] = s;
  }
  // patch_feat into gin
#pragma unroll
  for (int r = 0; r < 10; ++r) {
    int e = tid + 128 * r;
    if (e < 1188) gin[(e / 33) * FEAT + (e % 33)] = pf[r];
  }
  __syncthreads();

  // ---- phase 1: shape features + M1 -----------------------------------------
  for (int e = tid; e < 36 * 72; e += 128) {
    int n = e / 72, q = e % 72, m = q >> 1, kk = q & 1;
    gin[n * FEAT + 33 + q] = lh[m][kk] - lh[n][kk];
  }
  for (int e = tid; e < 144; e += 128) {
    int p = e / 36, n = e % 36;
    float s = 0.f;
#pragma unroll
    for (int h = 0; h < 16; ++h) s += A[p][h] * H[n * 16 + h];
    M1s[p][n] = s;
  }
  __syncthreads();

  // ---- phase 2: fused message + dropout + heads (warp p = point p) ----------
  const int p = warp;
  float acc[11];
#pragma unroll
  for (int o = 0; o < 11; ++o) acc[o] = 0.f;

#pragma unroll
  for (int r = 0; r < 4; ++r) {
    int f = lane + 32 * r;
    if (f < FEAT) {
      float s = 0.f;
#pragma unroll
      for (int n = 0; n < 36; ++n) s = fmaf(M1s[p][n], gin[n * FEAT + f], s);
      uint32_t g = (uint32_t)((b * 4 + p) * FEAT + f);
      float u1 = tf_uniform(k10, k11, g);
      float u2 = tf_uniform(k20, k21, g);
      float x1 = (u1 < 0.9f) ? s / 0.9f : 0.f;
      float x2 = (u2 < 0.9f) ? s / 0.9f : 0.f;
      acc[0] = fmaf(x1, wsm[0 * FEAT + f], acc[0]);
      acc[1] = fmaf(x1, wsm[1 * FEAT + f], acc[1]);
#pragma unroll
      for (int j = 0; j < 9; ++j)
        acc[2 + j] = fmaf(x2, wsm[(2 + j) * FEAT + f], acc[2 + j]);
    }
  }
#pragma unroll
  for (int o = 0; o < 11; ++o)
#pragma unroll
    for (int s = 16; s; s >>= 1) acc[o] += __shfl_xor_sync(0xffffffffu, acc[o], s);

  if (lane == 0) {
    float off0 = 1.f / (1.f + expf(-(acc[0] + l1b[0])));
    float off1 = 1.f / (1.f + expf(-(acc[1] + l1b[1])));
    float lg[9], mx = -1e30f;
#pragma unroll
    for (int j = 0; j < 9; ++j) { lg[j] = acc[2 + j] + l2b[j]; mx = fmaxf(mx, lg[j]); }
    float den = 0.f, s0 = 0.f, s1 = 0.f;
#pragma unroll
    for (int j = 0; j < 9; ++j) {
      float e = expf(lg[j] - mx);
      den += e;
      s0 += e * c_shift[j][0];
      s1 += e * c_shift[j][1];
    }
    s0 /= den; s1 /= den;
    out[b * 8 + p * 2 + 0] = (x[b * 8 + p * 2 + 0] + off0 * s0) * 255.f;
    out[b * 8 + p * 2 + 1] = (x[b * 8 + p * 2 + 1] + off1 * s1) * 255.f;
  }
}

// ---------------------------------------------------------------------------
extern "C" void kernel_launch(void* const* d_in, const int* in_sizes, int n_in,
                              void* d_out, int out_size)
{
  const float* d      = (const float*)d_in[0];
  const float* x      = (const float*)d_in[1];
  const float* conv_w = (const float*)d_in[2];
  const float* conv_b = (const float*)d_in[3];
  const float* H      = (const float*)d_in[4];
  const float* T      = (const float*)d_in[5];
  const float* W      = (const float*)d_in[6];
  const float* l1w    = (const float*)d_in[7];
  const float* l1b    = (const float*)d_in[8];
  const float* l2w    = (const float*)d_in[9];
  const float* l2b    = (const float*)d_in[10];
  float* out = (float*)d_out;

  cudaFuncSetAttribute(crop_conv_kernel,
                       cudaFuncAttributeMaxDynamicSharedMemorySize, SMEM_A);

  dim3 gridA(4, 32);
  crop_conv_kernel<<<gridA, 256, SMEM_A>>>(d, x, conv_w, conv_b);
  tail_kernel<<<32, 128>>>(x, H, T, W, l1w, l1b, l2w, l2b, out);
}

// round 5
// speedup vs baseline: 1.8384x; 1.8384x over previous
#include <cuda_runtime.h>
#include <cstdint>

#define CCH    33
#define KSZ    2112      // 33*8*8
#define FEAT   107
#define IMG    65536     // 256*256
#define QP     6         // crops per block
#define NPG    6         // patch groups (36/QP)
#define ROWS_B (QP * CCH * 8)          // 1584 rows per block
#define SMEM_BYTES (QP * KSZ * 4)      // 50688

// SHIFTS / 255 exactly as the reference table (note duplicated [0,8] at j=6)
__constant__ float c_shift[9][2] = {
  {-8.f/255.f,  0.f/255.f}, {-8.f/255.f,  8.f/255.f}, { 0.f/255.f,  8.f/255.f},
  { 8.f/255.f,  8.f/255.f}, { 8.f/255.f,  0.f/255.f}, { 8.f/255.f, -8.f/255.f},
  { 0.f/255.f,  8.f/255.f}, {-8.f/255.f, -8.f/255.f}, { 0.f/255.f,  0.f/255.f}
};

__device__ float g_patch_feat[32 * 36 * 33];
__device__ int   g_cnt[32];            // monotonic; %NPG==NPG-1 triggers tail

// ---------------------------------------------------------------------------
// threefry2x32 (JAX-compatible, 20 rounds) + partitionable uniform
// ---------------------------------------------------------------------------
__device__ __forceinline__ void threefry2x32(uint32_t k0, uint32_t k1,
                                             uint32_t x0, uint32_t x1,
                                             uint32_t& o0, uint32_t& o1)
{
  uint32_t ks[3] = {k0, k1, k0 ^ k1 ^ 0x1BD11BDAu};
  x0 += ks[0]; x1 += ks[1];
  const int R[2][4] = {{13, 15, 26, 6}, {17, 29, 16, 24}};
#pragma unroll
  for (int i = 0; i < 5; ++i) {
#pragma unroll
    for (int r = 0; r < 4; ++r) {
      x0 += x1;
      int rr = R[i & 1][r];
      x1 = (x1 << rr) | (x1 >> (32 - rr));
      x1 ^= x0;
    }
    x0 += ks[(i + 1) % 3];
    x1 += ks[(i + 2) % 3] + (uint32_t)(i + 1);
  }
  o0 = x0; o1 = x1;
}

__device__ __forceinline__ float tf_uniform(uint32_t k0, uint32_t k1, uint32_t g)
{
  uint32_t y0, y1;
  threefry2x32(k0, k1, 0u, g, y0, y1);
  uint32_t bits = y0 ^ y1;
  return __uint_as_float((bits >> 9) | 0x3f800000u) - 1.0f;
}

// ---------------------------------------------------------------------------
// Fused kernel: crops + conv (all blocks) ; tail (last block per batch).
// grid (NPG, 32), 256 threads, dynamic smem = QP*KSZ floats.
// ---------------------------------------------------------------------------
__global__ __launch_bounds__(256, 2)
void fused_kernel(const float* __restrict__ d, const float* __restrict__ x,
                  const float* __restrict__ conv_w, const float* __restrict__ conv_b,
                  const float* __restrict__ H,  const float* __restrict__ T,
                  const float* __restrict__ W,
                  const float* __restrict__ l1w, const float* __restrict__ l1b,
                  const float* __restrict__ l2w, const float* __restrict__ l2b,
                  float* __restrict__ out)
{
  extern __shared__ float smemf[];     // QP*KSZ floats (crop), aliased by tail
  __shared__ int s_ix[QP], s_iy[QP];
  __shared__ int s_flag;

  const int pg  = blockIdx.x;          // 0..5, crops pg*QP .. pg*QP+QP-1
  const int b   = blockIdx.y;
  const int tid = threadIdx.x;
  const int warp = tid >> 5, lane = tid & 31;

  // ---- crop coordinates (parallel replay, exact fp order) -------------------
  if (tid < 36) {
    const int idx = (tid / 9) * (tid % 9);
    float lx = x[b * 8 + (idx / 9) * 2 + 0];
    float ly = x[b * 8 + (idx / 9) * 2 + 1];
#pragma unroll
    for (int st = 0; st < 36; ++st) {
      int i = st / 9, j = st % 9;
      if (st <= tid && i * j == idx) { lx += c_shift[j][0]; ly += c_shift[j][1]; }
    }
    int rel = tid - pg * QP;
    if (rel >= 0 && rel < QP) {
      int ix = (int)rintf(lx * 255.f);
      int iy = (int)rintf((ly + 1.0f) * 255.f);
      s_ix[rel] = min(max(ix, 0), 255);
      s_iy[rel] = min(max(iy, 0), 255);
    }
  }
  __syncthreads();

  // ---- gather: one 32B row per thread-iter via 3 aligned LDG.128 ------------
  const float* db = d + (size_t)b * CCH * IMG;
  for (int rid = tid; rid < ROWS_B; rid += 256) {
    int q   = rid / 264;
    int rem = rid - q * 264;
    int c = rem >> 3, h = rem & 7;
    int ix = s_ix[q], iy = s_iy[q];
    int r    = ix - 4 + h;
    int col0 = iy - 4;
    int a    = col0 & 3;
    int base = col0 - a;
    const float* rowp = db + c * IMG + r * 256;
    float4 v0 = {0,0,0,0}, v1 = {0,0,0,0}, v2 = {0,0,0,0};
    bool rok = (unsigned)r < 256u;
    if (rok && (unsigned)base       < 256u) v0 = *(const float4*)(rowp + base);
    if (rok && (unsigned)(base + 4) < 256u) v1 = *(const float4*)(rowp + base + 4);
    if (rok && (unsigned)(base + 8) < 256u) v2 = *(const float4*)(rowp + base + 8);
    float4 r0, r1;
    if (a == 0)      { r0 = v0; r1 = v1; }
    else if (a == 1) { r0 = make_float4(v0.y, v0.z, v0.w, v1.x);
                       r1 = make_float4(v1.y, v1.z, v1.w, v2.x); }
    else if (a == 2) { r0 = make_float4(v0.z, v0.w, v1.x, v1.y);
                       r1 = make_float4(v1.z, v1.w, v2.x, v2.y); }
    else             { r0 = make_float4(v0.w, v1.x, v1.y, v1.z);
                       r1 = make_float4(v1.w, v2.x, v2.y, v2.z); }
    float* dst = smemf + q * KSZ + c * 64 + h * 8;
    *(float4*)dst       = r0;
    *(float4*)(dst + 4) = r1;
  }
  __syncthreads();

  // ---- conv: warp w handles outputs {w, w+8, w+16, w+24} (+32 on warp 0) ----
  float acc[4][QP];
  float accx[QP];
#pragma unroll
  for (int j = 0; j < 4; ++j)
#pragma unroll
    for (int q = 0; q < QP; ++q) acc[j][q] = 0.f;
#pragma unroll
  for (int q = 0; q < QP; ++q) accx[q] = 0.f;

  const float4* w4base = (const float4*)conv_w;
#pragma unroll 2
  for (int it = 0; it < 16; ++it) {
    int k4 = lane + it * 32;             // < 512
    float4 cv[QP];
#pragma unroll
    for (int q = 0; q < QP; ++q) cv[q] = *(const float4*)(smemf + q * KSZ + k4 * 4);
#pragma unroll
    for (int j = 0; j < 4; ++j) {
      float4 wv = __ldg(w4base + (warp + j * 8) * 528 + k4);
#pragma unroll
      for (int q = 0; q < QP; ++q) {
        acc[j][q] = fmaf(cv[q].x, wv.x, acc[j][q]);
        acc[j][q] = fmaf(cv[q].y, wv.y, acc[j][q]);
        acc[j][q] = fmaf(cv[q].z, wv.z, acc[j][q]);
        acc[j][q] = fmaf(cv[q].w, wv.w, acc[j][q]);
      }
    }
    if (warp == 0) {
      float4 wv = __ldg(w4base + 32 * 528 + k4);
#pragma unroll
      for (int q = 0; q < QP; ++q) {
        accx[q] = fmaf(cv[q].x, wv.x, accx[q]);
        accx[q] = fmaf(cv[q].y, wv.y, accx[q]);
        accx[q] = fmaf(cv[q].z, wv.z, accx[q]);
        accx[q] = fmaf(cv[q].w, wv.w, accx[q]);
      }
    }
  }
  { // tail iter: k4 in [512, 528)
    int k4 = lane + 512;
    if (k4 < 528) {
      float4 cv[QP];
#pragma unroll
      for (int q = 0; q < QP; ++q) cv[q] = *(const float4*)(smemf + q * KSZ + k4 * 4);
#pragma unroll
      for (int j = 0; j < 4; ++j) {
        float4 wv = __ldg(w4base + (warp + j * 8) * 528 + k4);
#pragma unroll
        for (int q = 0; q < QP; ++q) {
          acc[j][q] = fmaf(cv[q].x, wv.x, acc[j][q]);
          acc[j][q] = fmaf(cv[q].y, wv.y, acc[j][q]);
          acc[j][q] = fmaf(cv[q].z, wv.z, acc[j][q]);
          acc[j][q] = fmaf(cv[q].w, wv.w, acc[j][q]);
        }
      }
      if (warp == 0) {
        float4 wv = __ldg(w4base + 32 * 528 + k4);
#pragma unroll
        for (int q = 0; q < QP; ++q) {
          accx[q] = fmaf(cv[q].x, wv.x, accx[q]);
          accx[q] = fmaf(cv[q].y, wv.y, accx[q]);
          accx[q] = fmaf(cv[q].z, wv.z, accx[q]);
          accx[q] = fmaf(cv[q].w, wv.w, accx[q]);
        }
      }
    }
  }

  // ---- reduce + write patch_feat -------------------------------------------
  float* pfb = g_patch_feat + ((size_t)b * 36 + pg * QP) * 33;
#pragma unroll
  for (int j = 0; j < 4; ++j) {
    int o = warp + j * 8;
#pragma unroll
    for (int q = 0; q < QP; ++q) {
      float s = acc[j][q];
#pragma unroll
      for (int sh = 16; sh; sh >>= 1) s += __shfl_xor_sync(0xffffffffu, s, sh);
      if (lane == 0) pfb[q * 33 + o] = s + conv_b[o];
    }
  }
  if (warp == 0) {
#pragma unroll
    for (int q = 0; q < QP; ++q) {
      float s = accx[q];
#pragma unroll
      for (int sh = 16; sh; sh >>= 1) s += __shfl_xor_sync(0xffffffffu, s, sh);
      if (lane == 0) pfb[q * 33 + 32] = s + conv_b[32];
    }
  }

  // ---- last-block-per-batch election ---------------------------------------
  __threadfence();
  __syncthreads();
  if (tid == 0) {
    int old = atomicAdd(&g_cnt[b], 1);
    s_flag = ((old % NPG) == (NPG - 1)) ? 1 : 0;
  }
  __syncthreads();
  if (!s_flag) return;

  // ======================= TAIL (one block per batch) ========================
  // alias dynamic smem (crop no longer needed)
  float* gin = smemf;                 // 36*107 = 3852
  float* wsm = smemf + 3852;          // 11*107 = 1177
  float* lhv = smemf + 3852 + 1184;   // 72
  float* Am  = lhv + 72;              // 64
  float* M1m = Am + 64;               // 144

  uint32_t k10, k11, k20, k21;
  threefry2x32(0u, 42u, 0u, 0u, k10, k11);
  threefry2x32(0u, 42u, 0u, 1u, k20, k21);

  if (tid < 36) {
    float lx = x[b * 8 + (tid / 9) * 2 + 0];
    float ly = x[b * 8 + (tid / 9) * 2 + 1];
#pragma unroll
    for (int st = 0; st < 36; ++st) {
      int i = st / 9, j = st % 9;
      if (i * j == tid) { lx += c_shift[j][0]; ly += c_shift[j][1]; }
    }
    lhv[tid * 2 + 0] = lx; lhv[tid * 2 + 1] = ly;
    gin[tid * FEAT + 105] = lx;
    gin[tid * FEAT + 106] = ly;
  }
  if (tid >= 64 && tid < 128) {
    int p = (tid - 64) >> 4, h = (tid - 64) & 15;
    float wh = W[h], s = 0.f;
    for (int n = 0; n < 36; ++n) s += T[p * 36 + n] * (H[n * 16 + h] * wh);
    Am[p * 16 + h] = s;
  }
  for (int e = tid; e < 1188; e += 256)
    gin[(e / 33) * FEAT + (e % 33)] = __ldcg(&g_patch_feat[b * 1188 + e]);
  for (int e = tid; e < 11 * FEAT; e += 256)
    wsm[e] = (e < 2 * FEAT) ? l1w[e] : l2w[e - 2 * FEAT];
  __syncthreads();

  for (int e = tid; e < 36 * 72; e += 256) {
    int n = e / 72, qq = e % 72, m = qq >> 1, kk = qq & 1;
    gin[n * FEAT + 33 + qq] = lhv[m * 2 + kk] - lhv[n * 2 + kk];
  }
  if (tid < 144) {
    int p = tid / 36, n = tid % 36;
    float s = 0.f;
#pragma unroll
    for (int h = 0; h < 16; ++h) s += Am[p * 16 + h] * H[n * 16 + h];
    M1m[p * 36 + n] = s;
  }
  __syncthreads();

  if (warp < 4) {
    const int p = warp;
    float hacc[11];
#pragma unroll
    for (int o = 0; o < 11; ++o) hacc[o] = 0.f;
#pragma unroll
    for (int r = 0; r < 4; ++r) {
      int f = lane + 32 * r;
      if (f < FEAT) {
        float s = 0.f;
#pragma unroll
        for (int n = 0; n < 36; ++n) s = fmaf(M1m[p * 36 + n], gin[n * FEAT + f], s);
        uint32_t g = (uint32_t)((b * 4 + p) * FEAT + f);
        float u1 = tf_uniform(k10, k11, g);
        float u2 = tf_uniform(k20, k21, g);
        float x1 = (u1 < 0.9f) ? s / 0.9f : 0.f;
        float x2 = (u2 < 0.9f) ? s / 0.9f : 0.f;
        hacc[0] = fmaf(x1, wsm[0 * FEAT + f], hacc[0]);
        hacc[1] = fmaf(x1, wsm[1 * FEAT + f], hacc[1]);
#pragma unroll
        for (int j = 0; j < 9; ++j)
          hacc[2 + j] = fmaf(x2, wsm[(2 + j) * FEAT + f], hacc[2 + j]);
      }
    }
#pragma unroll
    for (int o = 0; o < 11; ++o)
#pragma unroll
      for (int sh = 16; sh; sh >>= 1)
        hacc[o] += __shfl_xor_sync(0xffffffffu, hacc[o], sh);

    if (lane == 0) {
      float off0 = 1.f / (1.f + expf(-(hacc[0] + l1b[0])));
      float off1 = 1.f / (1.f + expf(-(hacc[1] + l1b[1])));
      float lg[9], mx = -1e30f;
#pragma unroll
      for (int j = 0; j < 9; ++j) { lg[j] = hacc[2 + j] + l2b[j]; mx = fmaxf(mx, lg[j]); }
      float den = 0.f, s0 = 0.f, s1 = 0.f;
#pragma unroll
      for (int j = 0; j < 9; ++j) {
        float e = expf(lg[j] - mx);
        den += e;
        s0 += e * c_shift[j][0];
        s1 += e * c_shift[j][1];
      }
      s0 /= den; s1 /= den;
      out[b * 8 + p * 2 + 0] = (x[b * 8 + p * 2 + 0] + off0 * s0) * 255.f;
      out[b * 8 + p * 2 + 1] = (x[b * 8 + p * 2 + 1] + off1 * s1) * 255.f;
    }
  }
}

// ---------------------------------------------------------------------------
extern "C" void kernel_launch(void* const* d_in, const int* in_sizes, int n_in,
                              void* d_out, int out_size)
{
  const float* d      = (const float*)d_in[0];
  const float* x      = (const float*)d_in[1];
  const float* conv_w = (const float*)d_in[2];
  const float* conv_b = (const float*)d_in[3];
  const float* H      = (const float*)d_in[4];
  const float* T      = (const float*)d_in[5];
  const float* W      = (const float*)d_in[6];
  const float* l1w    = (const float*)d_in[7];
  const float* l1b    = (const float*)d_in[8];
  const float* l2w    = (const float*)d_in[9];
  const float* l2b    = (const float*)d_in[10];
  float* out = (float*)d_out;

  static bool attr_set = false;
  if (!attr_set) {
    cudaFuncSetAttribute(fused_kernel,
                         cudaFuncAttributeMaxDynamicSharedMemorySize, SMEM_BYTES);
    attr_set = true;
  }

  dim3 grid(NPG, 32);
  fused_kernel<<<grid, 256, SMEM_BYTES>>>(d, x, conv_w, conv_b,
                                          H, T, W, l1w, l1b, l2w, l2b, out);
}